// round 10
// baseline (speedup 1.0000x reference)
#include <cuda_runtime.h>
#include <cuda_fp16.h>

// Dims fixed by the reference: x is (B=8, T=2048, F=128) float32.
#define BB 8
#define TT 2048
#define FF 128
#define NN (BB * TT * FF)           // 2,097,152
#define SB (TT * FF)                // 262144
#define ST (FF)                     // 128

#define TAU_F (1.0f / 6.0f)
#define NITERS 29                   // p updates (MAX_ITERS - 1 scan steps)

#define T2 2                        // t-rows per tile
#define NTILE (TT / T2)             // 1024
#define GRID 512                    // persistent blocks; ALL must be resident
#define TPB (NTILE / GRID)          // 2 tiles per block
#define NWARP 8
#define NT 256

// Ping-pong dual buffers in fp16 (math stays fp32). No runtime allocation.
__device__ __half gA0[NN], gA1[NN], gA2[NN];
__device__ __half gB0[NN], gB1[NN], gB2[NN];
__device__ int g_bar[32];           // one arrival counter per iteration

__device__ __forceinline__ float4 ld4(const float* __restrict__ p, int idx) {
    return *reinterpret_cast<const float4*>(p + idx);
}
__device__ __forceinline__ void st4(float* __restrict__ p, int idx, float4 v) {
    *reinterpret_cast<float4*>(p + idx) = v;
}
__device__ __forceinline__ float4 u2tof4(uint2 u) {
    __half2 h0 = *reinterpret_cast<__half2*>(&u.x);
    __half2 h1 = *reinterpret_cast<__half2*>(&u.y);
    float2 f0 = __half22float2(h0);
    float2 f1 = __half22float2(h1);
    return make_float4(f0.x, f0.y, f1.x, f1.y);
}
__device__ __forceinline__ uint2 f4tou2(float4 v) {
    __half2 h0 = __floats2half2_rn(v.x, v.y);
    __half2 h1 = __floats2half2_rn(v.z, v.w);
    uint2 u;
    u.x = *reinterpret_cast<unsigned*>(&h0);
    u.y = *reinterpret_cast<unsigned*>(&h1);
    return u;
}
__device__ __forceinline__ float4 f4sub(float4 a, float4 b) {
    return make_float4(a.x - b.x, a.y - b.y, a.z - b.z, a.w - b.w);
}
__device__ __forceinline__ float4 f4add(float4 a, float4 b) {
    return make_float4(a.x + b.x, a.y + b.y, a.z + b.z, a.w + b.w);
}

// smem p tile: [comp][trow 0..3 = t0-1..t0+2][b][lane] fp16x4 raw.
#define SPI2(c, tr, b) ((((c) * 4 + (tr)) * BB + (b)) * 32)
// smem out tile: [trow 0..2 = t0..t0+2][b][lane] fp32x4.
#define SOI2(tr, b) (((tr) * BB + (b)) * 32)

__global__ void k_zero_bar() {
    if (threadIdx.x < 32) g_bar[threadIdx.x] = 0;
}

__global__ __launch_bounds__(NT, 4)
void k_persist(const float* __restrict__ img, const float* __restrict__ lam,
               const float* __restrict__ bias, float* __restrict__ out) {
    __shared__ uint2 s_p[3 * 4 * BB * 32];     // 24 KB
    __shared__ float4 s_o[3 * BB * 32];        // 12 KB

    const int b = threadIdx.x >> 5;            // warp == batch index
    const int lane = threadIdx.x & 31;         // == f4 index
    const float tw = TAU_F / lam[0];

    for (int it = 0; it < NITERS; ++it) {
        // it even writes A (it0 -> A); reads the other buffer (unused at it0).
        const __half* __restrict__ q0 = (it & 1) ? gA0 : gB0;
        const __half* __restrict__ q1 = (it & 1) ? gA1 : gB1;
        const __half* __restrict__ q2 = (it & 1) ? gA2 : gB2;
        __half* __restrict__ w0 = (it & 1) ? gB0 : gA0;
        __half* __restrict__ w1 = (it & 1) ? gB1 : gA1;
        __half* __restrict__ w2 = (it & 1) ? gB2 : gA2;

        for (int s = 0; s < TPB; ++s) {
            const int t0 = (blockIdx.x + s * GRID) * T2;

            // Phase L: load p rows [t0-1, t0+2] via L2 (__ldcg — L1 is stale
            // across SMs within a persistent launch). Skipped at it==0 (p=0).
            if (it > 0) {
#pragma unroll
                for (int tr = 0; tr < 4; ++tr) {
                    int t = t0 - 1 + tr;
                    if (t >= 0 && t < TT) {
                        int idx = b * SB + t * ST + lane * 4;
                        s_p[SPI2(0, tr, b) + lane] =
                            __ldcg(reinterpret_cast<const uint2*>(q0 + idx));
                        s_p[SPI2(1, tr, b) + lane] =
                            __ldcg(reinterpret_cast<const uint2*>(q1 + idx));
                        s_p[SPI2(2, tr, b) + lane] =
                            __ldcg(reinterpret_cast<const uint2*>(q2 + idx));
                    }
                }
            }
            __syncthreads();

            // Phase A: out = img + div(p) for rows [t0, t0+2] -> s_o.
#pragma unroll
            for (int tr = 0; tr < 3; ++tr) {
                int t = t0 + tr;
                if (t < TT) {
                    float4 d = ld4(img, b * SB + t * ST + lane * 4);
                    if (it > 0) {
                        float4 a0 = u2tof4(s_p[SPI2(0, tr + 1, b) + lane]);
                        float4 a1 = u2tof4(s_p[SPI2(1, tr + 1, b) + lane]);
                        float4 a2 = u2tof4(s_p[SPI2(2, tr + 1, b) + lane]);
                        d = f4sub(f4sub(f4sub(d, a0), a1), a2);
                        if (b > 0)
                            d = f4add(d, u2tof4(s_p[SPI2(0, tr + 1, b - 1) + lane]));
                        if (t > 0)
                            d = f4add(d, u2tof4(s_p[SPI2(1, tr, b) + lane]));
                        float prevw = __shfl_up_sync(0xffffffffu, a2.w, 1);
                        if (lane > 0) d.x += prevw;
                        d.y += a2.x; d.z += a2.y; d.w += a2.z;
                    }
                    s_o[SOI2(tr, b) + lane] = d;
                }
            }
            __syncthreads();

            // Phase B: update p for rows [t0, t0+1] -> global (write buffer).
#pragma unroll
            for (int tr = 0; tr < 2; ++tr) {
                int t = t0 + tr;
                int idx = b * SB + t * ST + lane * 4;

                float4 o = s_o[SOI2(tr, b) + lane];
                float4 gb = make_float4(0, 0, 0, 0);
                float4 gt = make_float4(0, 0, 0, 0);
                float4 gf;
                if (b < BB - 1) gb = f4sub(s_o[SOI2(tr, b + 1) + lane], o);
                if (t < TT - 1) gt = f4sub(s_o[SOI2(tr + 1, b) + lane], o);
                float nx = __shfl_down_sync(0xffffffffu, o.x, 1);
                gf.x = o.y - o.x; gf.y = o.z - o.y; gf.z = o.w - o.z;
                gf.w = (lane < 31) ? (nx - o.w) : 0.0f;

                float4 a0 = make_float4(0, 0, 0, 0);
                float4 a1 = make_float4(0, 0, 0, 0);
                float4 a2 = make_float4(0, 0, 0, 0);
                if (it > 0) {
                    a0 = u2tof4(s_p[SPI2(0, tr + 1, b) + lane]);
                    a1 = u2tof4(s_p[SPI2(1, tr + 1, b) + lane]);
                    a2 = u2tof4(s_p[SPI2(2, tr + 1, b) + lane]);
                }
                float4 o0, o1, o2;
#define UPD(c)                                                            \
                { float n = sqrtf(gb.c * gb.c + gt.c * gt.c + gf.c * gf.c); \
                  float inv = __fdividef(1.0f, n * tw + 1.0f);            \
                  o0.c = (a0.c - TAU_F * gb.c) * inv;                     \
                  o1.c = (a1.c - TAU_F * gt.c) * inv;                     \
                  o2.c = (a2.c - TAU_F * gf.c) * inv; }
                UPD(x) UPD(y) UPD(z) UPD(w)
#undef UPD
                *reinterpret_cast<uint2*>(w0 + idx) = f4tou2(o0);
                *reinterpret_cast<uint2*>(w1 + idx) = f4tou2(o1);
                *reinterpret_cast<uint2*>(w2 + idx) = f4tou2(o2);
            }
            __syncthreads();
        }

        // ---- grid barrier (all 512 blocks resident by construction) ----
        __threadfence();                       // make this thread's p writes visible
        __syncthreads();                       // all block threads fenced
        if (threadIdx.x == 0) {
            atomicAdd(&g_bar[it], 1);
            while (__ldcg(&g_bar[it]) < GRID) __nanosleep(64);
            __threadfence();                   // acquire
        }
        __syncthreads();
    }

    // ---- final: out = img + div(p_final) + bias; p_final is in A (it28 even)
    for (int s = 0; s < TPB; ++s) {
        const int t0 = (blockIdx.x + s * GRID) * T2;
#pragma unroll
        for (int tr = 0; tr < 4; ++tr) {       // rows [t0-1, t0+2]; t0+2 unused but harmless
            int t = t0 - 1 + tr;
            if (t >= 0 && t < TT) {
                int idx = b * SB + t * ST + lane * 4;
                s_p[SPI2(0, tr, b) + lane] =
                    __ldcg(reinterpret_cast<const uint2*>(gA0 + idx));
                s_p[SPI2(1, tr, b) + lane] =
                    __ldcg(reinterpret_cast<const uint2*>(gA1 + idx));
                s_p[SPI2(2, tr, b) + lane] =
                    __ldcg(reinterpret_cast<const uint2*>(gA2 + idx));
            }
        }
        __syncthreads();
#pragma unroll
        for (int tr = 0; tr < 2; ++tr) {
            int t = t0 + tr;
            int idx = b * SB + t * ST + lane * 4;
            float4 d = ld4(img, idx);
            float4 a0 = u2tof4(s_p[SPI2(0, tr + 1, b) + lane]);
            float4 a1 = u2tof4(s_p[SPI2(1, tr + 1, b) + lane]);
            float4 a2 = u2tof4(s_p[SPI2(2, tr + 1, b) + lane]);
            d = f4sub(f4sub(f4sub(d, a0), a1), a2);
            if (b > 0) d = f4add(d, u2tof4(s_p[SPI2(0, tr + 1, b - 1) + lane]));
            if (t > 0) d = f4add(d, u2tof4(s_p[SPI2(1, tr, b) + lane]));
            float prevw = __shfl_up_sync(0xffffffffu, a2.w, 1);
            if (lane > 0) d.x += prevw;
            d.y += a2.x; d.z += a2.y; d.w += a2.z;
            d = f4add(d, ld4(bias, lane * 4));
            st4(out, idx, d);
        }
        __syncthreads();
    }
}

extern "C" void kernel_launch(void* const* d_in, const int* in_sizes, int n_in,
                              void* d_out, int out_size) {
    const float* x   = (const float*)d_in[0];   // (8, 2048, 128)
    const float* lam = (const float*)d_in[1];   // (1, 1)
    const float* b   = (const float*)d_in[2];   // (1, 1, 128)
    float* out = (float*)d_out;

    k_zero_bar<<<1, 32>>>();                    // reset barrier counters
    k_persist<<<GRID, NT>>>(x, lam, b, out);    // one persistent kernel
}

// round 11
// speedup vs baseline: 1.2593x; 1.2593x over previous
#include <cuda_runtime.h>
#include <cuda_fp16.h>

// Dims fixed by the reference: x is (B=8, T=2048, F=128) float32.
#define BB 8
#define TT 2048
#define FF 128
#define NN (BB * TT * FF)           // 2,097,152
#define SB (TT * FF)                // 262144
#define ST (FF)                     // 128

#define TAU_F (1.0f / 6.0f)
#define NFUSED 28                   // updates #2..#29 (update #1 is k_first)

#define TTILE 2                     // T-rows per block tile (grid = 1024)
#define NWARP 8
#define NTHREADS (NWARP * 32)       // 256
#define F4 (FF / 4)                 // 32 float4/half4 per row == one warp

// Ping-pong dual buffers in fp16 (math stays fp32). No runtime allocation.
__device__ __half g_pa0[NN], g_pa1[NN], g_pa2[NN];
__device__ __half g_pb0[NN], g_pb1[NN], g_pb2[NN];

__device__ __forceinline__ float4 ld4(const float* __restrict__ p, int idx) {
    return *reinterpret_cast<const float4*>(p + idx);
}
__device__ __forceinline__ void st4(float* __restrict__ p, int idx, float4 v) {
    *reinterpret_cast<float4*>(p + idx) = v;
}
// 8-byte vector load of 4 halves -> float4
__device__ __forceinline__ float4 ldh4(const __half* __restrict__ p, int idx) {
    uint2 u = *reinterpret_cast<const uint2*>(p + idx);
    __half2 h0 = *reinterpret_cast<__half2*>(&u.x);
    __half2 h1 = *reinterpret_cast<__half2*>(&u.y);
    float2 f0 = __half22float2(h0);
    float2 f1 = __half22float2(h1);
    return make_float4(f0.x, f0.y, f1.x, f1.y);
}
__device__ __forceinline__ void sth4(__half* __restrict__ p, int idx, float4 v) {
    __half2 h0 = __floats2half2_rn(v.x, v.y);
    __half2 h1 = __floats2half2_rn(v.z, v.w);
    uint2 u;
    u.x = *reinterpret_cast<unsigned*>(&h0);
    u.y = *reinterpret_cast<unsigned*>(&h1);
    *reinterpret_cast<uint2*>(p + idx) = u;
}
__device__ __forceinline__ float4 f4sub(float4 a, float4 b) {
    return make_float4(a.x - b.x, a.y - b.y, a.z - b.z, a.w - b.w);
}
__device__ __forceinline__ float4 f4add(float4 a, float4 b) {
    return make_float4(a.x + b.x, a.y + b.y, a.z + b.z, a.w + b.w);
}

// ---------------------------------------------------------------------------
// k_first: p = 0  =>  out = img, g = grad(img). Writes pA (fp16).
// ---------------------------------------------------------------------------
__global__ __launch_bounds__(NTHREADS)
void k_first(const float* __restrict__ img, const float* __restrict__ lam) {
    int tid = blockIdx.x * blockDim.x + threadIdx.x;   // float4 index
    if (tid >= NN / 4) return;
    int lane = tid & 31;                               // == f4
    int t = (tid >> 5) & (TT - 1);
    int b = tid >> 16;
    int idx = tid * 4;

    float4 o = ld4(img, idx);
    float4 gb = make_float4(0, 0, 0, 0), gt = make_float4(0, 0, 0, 0), gf;
    if (b < BB - 1) gb = f4sub(ld4(img, idx + SB), o);
    if (t < TT - 1) gt = f4sub(ld4(img, idx + ST), o);
    float nx = __shfl_down_sync(0xffffffffu, o.x, 1);
    gf.x = o.y - o.x; gf.y = o.z - o.y; gf.z = o.w - o.z;
    gf.w = (lane < 31) ? (nx - o.w) : 0.0f;            // f==127 boundary

    float tw = TAU_F / lam[0];
    float4 r0, r1, r2;
#define FIRST_UPD(c)                                                     \
    { float n = sqrtf(gb.c * gb.c + gt.c * gt.c + gf.c * gf.c);          \
      float inv = __fdividef(1.0f, n * tw + 1.0f);                       \
      r0.c = (-TAU_F * gb.c) * inv;                                      \
      r1.c = (-TAU_F * gt.c) * inv;                                      \
      r2.c = (-TAU_F * gf.c) * inv; }
    FIRST_UPD(x) FIRST_UPD(y) FIRST_UPD(z) FIRST_UPD(w)
#undef FIRST_UPD
    sth4(g_pa0, idx, r0);
    sth4(g_pa1, idx, r1);
    sth4(g_pa2, idx, r2);
}

// ---------------------------------------------------------------------------
// k_fused: one Chambolle step. Block tile = (all 8 b) x (TTILE t-rows) x (F).
// Phase A: out = img + div(p_in) into smem (fp32) for TTILE+1 t-rows.
// Phase B: gradients from smem, update p_out (fp16). Ping-pong p buffers.
// __launch_bounds__(256, 7): cap regs ~36 so 7 blocks/SM -> capacity 1036
// blocks >= grid 1024 -> SINGLE wave (R8's 45 regs gave 5/SM = 1.38 waves
// with a 284-block straggler tail).
// ---------------------------------------------------------------------------
template <bool A2B>
__global__ __launch_bounds__(NTHREADS, 7)
void k_fused(const float* __restrict__ img, const float* __restrict__ lam) {
    const __half* __restrict__ q0 = A2B ? g_pa0 : g_pb0;
    const __half* __restrict__ q1 = A2B ? g_pa1 : g_pb1;
    const __half* __restrict__ q2 = A2B ? g_pa2 : g_pb2;
    __half* __restrict__ r0 = A2B ? g_pb0 : g_pa0;
    __half* __restrict__ r1 = A2B ? g_pb1 : g_pa1;
    __half* __restrict__ r2 = A2B ? g_pb2 : g_pa2;

    __shared__ float4 s_out[BB][TTILE + 1][F4];        // 8*3*32*16 = 12 KB

    int warp = threadIdx.x >> 5;
    int lane = threadIdx.x & 31;                        // == f4
    int t0 = blockIdx.x * TTILE;
    float tw = TAU_F / lam[0];

    // Phase A: 8*(TTILE+1) = 24 rows over 8 warps (3 each). Guards row-uniform.
#pragma unroll
    for (int r = warp; r < BB * (TTILE + 1); r += NWARP) {
        int b = r / (TTILE + 1);
        int trow = r - b * (TTILE + 1);
        int t = t0 + trow;
        if (t < TT) {
            int idx = b * SB + t * ST + lane * 4;
            float4 d = ld4(img, idx);
            float4 a0 = ldh4(q0, idx);
            float4 a1 = ldh4(q1, idx);
            float4 a2 = ldh4(q2, idx);
            d = f4sub(f4sub(f4sub(d, a0), a1), a2);
            if (b > 0) d = f4add(d, ldh4(q0, idx - SB));
            if (t > 0) d = f4add(d, ldh4(q1, idx - ST));
            // + p2[f-1]: within-vector for y,z,w; lane-1's .w for x (0 at f==0)
            float prevw = __shfl_up_sync(0xffffffffu, a2.w, 1);
            if (lane > 0) d.x += prevw;
            d.y += a2.x; d.z += a2.y; d.w += a2.z;
            s_out[b][trow][lane] = d;
        }
    }
    __syncthreads();

    // Phase B: 8*TTILE = 16 rows over 8 warps (2 each).
#pragma unroll
    for (int r = warp; r < BB * TTILE; r += NWARP) {
        int b = r >> 1;                                 // r / TTILE
        int trow = r & (TTILE - 1);
        int t = t0 + trow;
        int idx = b * SB + t * ST + lane * 4;

        float4 o = s_out[b][trow][lane];
        float4 gb = make_float4(0, 0, 0, 0), gt = make_float4(0, 0, 0, 0), gf;
        if (b < BB - 1) gb = f4sub(s_out[b + 1][trow][lane], o);
        if (t < TT - 1) gt = f4sub(s_out[b][trow + 1][lane], o);
        float nx = __shfl_down_sync(0xffffffffu, o.x, 1);
        gf.x = o.y - o.x; gf.y = o.z - o.y; gf.z = o.w - o.z;
        gf.w = (lane < 31) ? (nx - o.w) : 0.0f;

        float4 a0 = ldh4(q0, idx);
        float4 a1 = ldh4(q1, idx);
        float4 a2 = ldh4(q2, idx);
        float4 o0, o1, o2;
#define UPD(c)                                                            \
        { float n = sqrtf(gb.c * gb.c + gt.c * gt.c + gf.c * gf.c);       \
          float inv = __fdividef(1.0f, n * tw + 1.0f);                    \
          o0.c = (a0.c - TAU_F * gb.c) * inv;                             \
          o1.c = (a1.c - TAU_F * gt.c) * inv;                             \
          o2.c = (a2.c - TAU_F * gf.c) * inv; }
        UPD(x) UPD(y) UPD(z) UPD(w)
#undef UPD
        sth4(r0, idx, o0);
        sth4(r1, idx, o1);
        sth4(r2, idx, o2);
    }
}

// ---------------------------------------------------------------------------
// k_final: out = img + div(pA) + bias[f]. One float4/thread.
// ---------------------------------------------------------------------------
__global__ __launch_bounds__(NTHREADS)
void k_final(const float* __restrict__ img, const float* __restrict__ bias,
             float* __restrict__ out) {
    int tid = blockIdx.x * blockDim.x + threadIdx.x;
    if (tid >= NN / 4) return;
    int lane = tid & 31;                               // == f4
    int t = (tid >> 5) & (TT - 1);
    int b = tid >> 16;
    int idx = tid * 4;

    float4 d = ld4(img, idx);
    float4 a0 = ldh4(g_pa0, idx);
    float4 a1 = ldh4(g_pa1, idx);
    float4 a2 = ldh4(g_pa2, idx);
    d = f4sub(f4sub(f4sub(d, a0), a1), a2);
    if (b > 0) d = f4add(d, ldh4(g_pa0, idx - SB));
    if (t > 0) d = f4add(d, ldh4(g_pa1, idx - ST));
    float prevw = __shfl_up_sync(0xffffffffu, a2.w, 1);
    if (lane > 0) d.x += prevw;
    d.y += a2.x; d.z += a2.y; d.w += a2.z;

    d = f4add(d, ld4(bias, lane * 4));
    st4(out, idx, d);
}

extern "C" void kernel_launch(void* const* d_in, const int* in_sizes, int n_in,
                              void* d_out, int out_size) {
    const float* x   = (const float*)d_in[0];   // (8, 2048, 128)
    const float* lam = (const float*)d_in[1];   // (1, 1)
    const float* b   = (const float*)d_in[2];   // (1, 1, 128)
    float* out = (float*)d_out;

    const int vblocks = (NN / 4 + NTHREADS - 1) / NTHREADS;   // 2048
    const int fblocks = TT / TTILE;                           // 1024

    k_first<<<vblocks, NTHREADS>>>(x, lam);

    for (int it = 0; it < NFUSED; ++it) {
        if ((it & 1) == 0)
            k_fused<true><<<fblocks, NTHREADS>>>(x, lam);   // A -> B
        else
            k_fused<false><<<fblocks, NTHREADS>>>(x, lam);  // B -> A
    }

    k_final<<<vblocks, NTHREADS>>>(x, b, out);
}

// round 12
// speedup vs baseline: 1.7451x; 1.3857x over previous
#include <cuda_runtime.h>
#include <cuda_fp16.h>

// Dims fixed by the reference: x is (B=8, T=2048, F=128) float32.
#define BB 8
#define TT 2048
#define FF 128
#define NN (BB * TT * FF)           // 2,097,152
#define SB (TT * FF)                // 262144
#define ST (FF)                     // 128

#define TAU_F (1.0f / 6.0f)
#define NFUSED 28                   // updates #2..#29 (update #1 is k_first)

#define TTILE 2                     // T-rows per block tile (grid = 1024)
#define NWARP 8
#define NTHREADS (NWARP * 32)       // 256

// Ping-pong dual buffers + fp16 image copy. No runtime allocation.
__device__ __half g_pa0[NN], g_pa1[NN], g_pa2[NN];
__device__ __half g_pb0[NN], g_pb1[NN], g_pb2[NN];
__device__ __half g_imgh[NN];

// ---------------- fp32 helpers (k_first / k_final only) --------------------
__device__ __forceinline__ float4 ld4(const float* __restrict__ p, int idx) {
    return *reinterpret_cast<const float4*>(p + idx);
}
__device__ __forceinline__ void st4(float* __restrict__ p, int idx, float4 v) {
    *reinterpret_cast<float4*>(p + idx) = v;
}
__device__ __forceinline__ float4 u2tof4(uint2 u) {
    __half2 h0 = *reinterpret_cast<__half2*>(&u.x);
    __half2 h1 = *reinterpret_cast<__half2*>(&u.y);
    float2 f0 = __half22float2(h0);
    float2 f1 = __half22float2(h1);
    return make_float4(f0.x, f0.y, f1.x, f1.y);
}
__device__ __forceinline__ uint2 f4tou2(float4 v) {
    __half2 h0 = __floats2half2_rn(v.x, v.y);
    __half2 h1 = __floats2half2_rn(v.z, v.w);
    uint2 u;
    u.x = *reinterpret_cast<unsigned*>(&h0);
    u.y = *reinterpret_cast<unsigned*>(&h1);
    return u;
}
__device__ __forceinline__ float4 ldh4(const __half* __restrict__ p, int idx) {
    return u2tof4(*reinterpret_cast<const uint2*>(p + idx));
}
__device__ __forceinline__ void sth4(__half* __restrict__ p, int idx, float4 v) {
    *reinterpret_cast<uint2*>(p + idx) = f4tou2(v);
}
__device__ __forceinline__ float4 f4sub(float4 a, float4 b) {
    return make_float4(a.x - b.x, a.y - b.y, a.z - b.z, a.w - b.w);
}
__device__ __forceinline__ float4 f4add(float4 a, float4 b) {
    return make_float4(a.x + b.x, a.y + b.y, a.z + b.z, a.w + b.w);
}

// ---------------- half2 helpers (k_fused) ----------------------------------
struct H4 { __half2 lo, hi; };                 // 4 halves = one uint2
__device__ __forceinline__ H4 ldH4(const __half* __restrict__ p, int idx) {
    uint2 u = *reinterpret_cast<const uint2*>(p + idx);
    H4 r;
    r.lo = *reinterpret_cast<__half2*>(&u.x);
    r.hi = *reinterpret_cast<__half2*>(&u.y);
    return r;
}
__device__ __forceinline__ void stH4(__half* __restrict__ p, int idx, H4 v) {
    uint2 u;
    u.x = *reinterpret_cast<unsigned*>(&v.lo);
    u.y = *reinterpret_cast<unsigned*>(&v.hi);
    *reinterpret_cast<uint2*>(p + idx) = u;
}
__device__ __forceinline__ unsigned h2u(__half2 h) {
    return *reinterpret_cast<unsigned*>(&h);
}
__device__ __forceinline__ __half2 u2h(unsigned u) {
    return *reinterpret_cast<__half2*>(&u);
}

// ---------------------------------------------------------------------------
// k_first: p = 0  =>  out = img, g = grad(img). Writes pA (fp16) + img_h.
// fp32 math (runs once).
// ---------------------------------------------------------------------------
__global__ __launch_bounds__(NTHREADS)
void k_first(const float* __restrict__ img, const float* __restrict__ lam) {
    int tid = blockIdx.x * blockDim.x + threadIdx.x;   // float4 index
    if (tid >= NN / 4) return;
    int lane = tid & 31;                               // == f4
    int t = (tid >> 5) & (TT - 1);
    int b = tid >> 16;
    int idx = tid * 4;

    float4 o = ld4(img, idx);
    *reinterpret_cast<uint2*>(g_imgh + idx) = f4tou2(o);   // fp16 image copy

    float4 gb = make_float4(0, 0, 0, 0), gt = make_float4(0, 0, 0, 0), gf;
    if (b < BB - 1) gb = f4sub(ld4(img, idx + SB), o);
    if (t < TT - 1) gt = f4sub(ld4(img, idx + ST), o);
    float nx = __shfl_down_sync(0xffffffffu, o.x, 1);
    gf.x = o.y - o.x; gf.y = o.z - o.y; gf.z = o.w - o.z;
    gf.w = (lane < 31) ? (nx - o.w) : 0.0f;            // f==127 boundary

    float tw = TAU_F / lam[0];
    float4 r0, r1, r2;
#define FIRST_UPD(c)                                                     \
    { float n = sqrtf(gb.c * gb.c + gt.c * gt.c + gf.c * gf.c);          \
      float inv = __fdividef(1.0f, n * tw + 1.0f);                       \
      r0.c = (-TAU_F * gb.c) * inv;                                      \
      r1.c = (-TAU_F * gt.c) * inv;                                      \
      r2.c = (-TAU_F * gf.c) * inv; }
    FIRST_UPD(x) FIRST_UPD(y) FIRST_UPD(z) FIRST_UPD(w)
#undef FIRST_UPD
    sth4(g_pa0, idx, r0);
    sth4(g_pa1, idx, r1);
    sth4(g_pa2, idx, r2);
}

// ---------------------------------------------------------------------------
// k_fused: one Chambolle step, native half2 SIMD.
// Tile = (all 8 b) x (TTILE t-rows) x (full F). One warp = one (b,t) row.
// Phase A: out = img_h + div(p) -> smem (fp16).  Phase B: grads + p update.
// ---------------------------------------------------------------------------
template <bool A2B>
__global__ __launch_bounds__(NTHREADS, 7)
void k_fused(const float* __restrict__ lam) {
    const __half* __restrict__ q0 = A2B ? g_pa0 : g_pb0;
    const __half* __restrict__ q1 = A2B ? g_pa1 : g_pb1;
    const __half* __restrict__ q2 = A2B ? g_pa2 : g_pb2;
    __half* __restrict__ w0 = A2B ? g_pb0 : g_pa0;
    __half* __restrict__ w1 = A2B ? g_pb1 : g_pa1;
    __half* __restrict__ w2 = A2B ? g_pb2 : g_pa2;

    __shared__ uint2 s_out[BB][TTILE + 1][32];          // fp16 out: 6 KB

    const int warp = threadIdx.x >> 5;
    const int lane = threadIdx.x & 31;                  // == f4 index
    const int t0 = blockIdx.x * TTILE;

    const float twf = TAU_F / lam[0];
    const __half2 tw2 = __float2half2_rn(twf);
    const __half2 one2 = __float2half2_rn(1.0f);
    const __half2 ntau2 = __float2half2_rn(-TAU_F);
    const __half2 zero2 = __float2half2_rn(0.0f);
    const __half zeroh = __float2half(0.0f);

    // Phase A: 8*(TTILE+1) = 24 rows over 8 warps (3 each). Guards row-uniform.
#pragma unroll
    for (int r = warp; r < BB * (TTILE + 1); r += NWARP) {
        int b = r / (TTILE + 1);
        int trow = r - b * (TTILE + 1);
        int t = t0 + trow;
        if (t < TT) {
            int idx = b * SB + t * ST + lane * 4;
            H4 im = ldH4(g_imgh, idx);
            H4 a0 = ldH4(q0, idx);
            H4 a1 = ldH4(q1, idx);
            H4 a2 = ldH4(q2, idx);
            __half2 dlo = __hsub2(__hsub2(__hsub2(im.lo, a0.lo), a1.lo), a2.lo);
            __half2 dhi = __hsub2(__hsub2(__hsub2(im.hi, a0.hi), a1.hi), a2.hi);
            if (b > 0) {
                H4 pb = ldH4(q0, idx - SB);
                dlo = __hadd2(dlo, pb.lo); dhi = __hadd2(dhi, pb.hi);
            }
            if (t > 0) {
                H4 pt = ldH4(q1, idx - ST);
                dlo = __hadd2(dlo, pt.lo); dhi = __hadd2(dhi, pt.hi);
            }
            // + p2[f-1]: shift a2 right by one element across the warp row.
            unsigned prevw = __shfl_up_sync(0xffffffffu, h2u(a2.hi), 1);
            __half pe3 = (lane > 0)
                ? __ushort_as_half((unsigned short)(prevw >> 16)) : zeroh;
            __half2 shlo = __halves2half2(pe3, __low2half(a2.lo));
            __half2 shhi = __halves2half2(__high2half(a2.lo), __low2half(a2.hi));
            dlo = __hadd2(dlo, shlo); dhi = __hadd2(dhi, shhi);
            uint2 u; u.x = h2u(dlo); u.y = h2u(dhi);
            s_out[b][trow][lane] = u;
        }
    }
    __syncthreads();

    // Phase B: 8*TTILE = 16 rows over 8 warps (2 each).
#pragma unroll
    for (int r = warp; r < BB * TTILE; r += NWARP) {
        int b = r >> 1;                                 // r / TTILE
        int trow = r & (TTILE - 1);
        int t = t0 + trow;
        int idx = b * SB + t * ST + lane * 4;

        uint2 ou = s_out[b][trow][lane];
        __half2 olo = u2h(ou.x), ohi = u2h(ou.y);

        __half2 gblo = zero2, gbhi = zero2, gtlo = zero2, gthi = zero2;
        if (b < BB - 1) {
            uint2 nu = s_out[b + 1][trow][lane];
            gblo = __hsub2(u2h(nu.x), olo);
            gbhi = __hsub2(u2h(nu.y), ohi);
        }
        if (t < TT - 1) {
            uint2 nu = s_out[b][trow + 1][lane];
            gtlo = __hsub2(u2h(nu.x), olo);
            gthi = __hsub2(u2h(nu.y), ohi);
        }
        // gf: out shifted left by one element; last element (f==127) -> 0.
        unsigned nextw = __shfl_down_sync(0xffffffffu, ou.x, 1);
        __half ne0 = (lane < 31)
            ? __ushort_as_half((unsigned short)(nextw & 0xffff))
            : __high2half(ohi);                         // makes gf.w == 0
        __half2 sllo = __halves2half2(__high2half(olo), __low2half(ohi));
        __half2 slhi = __halves2half2(__high2half(ohi), ne0);
        __half2 gflo = __hsub2(sllo, olo);
        __half2 gfhi = __hsub2(slhi, ohi);

        __half2 n2lo = __hfma2(gblo, gblo,
                        __hfma2(gtlo, gtlo, __hmul2(gflo, gflo)));
        __half2 n2hi = __hfma2(gbhi, gbhi,
                        __hfma2(gthi, gthi, __hmul2(gfhi, gfhi)));
        __half2 invlo = h2rcp(__hfma2(h2sqrt(n2lo), tw2, one2));
        __half2 invhi = h2rcp(__hfma2(h2sqrt(n2hi), tw2, one2));

        H4 a0 = ldH4(q0, idx);
        H4 a1 = ldH4(q1, idx);
        H4 a2 = ldH4(q2, idx);
        H4 o0, o1, o2;
        o0.lo = __hmul2(__hfma2(gblo, ntau2, a0.lo), invlo);
        o0.hi = __hmul2(__hfma2(gbhi, ntau2, a0.hi), invhi);
        o1.lo = __hmul2(__hfma2(gtlo, ntau2, a1.lo), invlo);
        o1.hi = __hmul2(__hfma2(gthi, ntau2, a1.hi), invhi);
        o2.lo = __hmul2(__hfma2(gflo, ntau2, a2.lo), invlo);
        o2.hi = __hmul2(__hfma2(gfhi, ntau2, a2.hi), invhi);
        stH4(w0, idx, o0);
        stH4(w1, idx, o1);
        stH4(w2, idx, o2);
    }
}

// ---------------------------------------------------------------------------
// k_final: out = img + div(pA) + bias[f]. fp32 math.
// ---------------------------------------------------------------------------
__global__ __launch_bounds__(NTHREADS)
void k_final(const float* __restrict__ img, const float* __restrict__ bias,
             float* __restrict__ out) {
    int tid = blockIdx.x * blockDim.x + threadIdx.x;
    if (tid >= NN / 4) return;
    int lane = tid & 31;                               // == f4
    int t = (tid >> 5) & (TT - 1);
    int b = tid >> 16;
    int idx = tid * 4;

    float4 d = ld4(img, idx);
    float4 a0 = ldh4(g_pa0, idx);
    float4 a1 = ldh4(g_pa1, idx);
    float4 a2 = ldh4(g_pa2, idx);
    d = f4sub(f4sub(f4sub(d, a0), a1), a2);
    if (b > 0) d = f4add(d, ldh4(g_pa0, idx - SB));
    if (t > 0) d = f4add(d, ldh4(g_pa1, idx - ST));
    float prevw = __shfl_up_sync(0xffffffffu, a2.w, 1);
    if (lane > 0) d.x += prevw;
    d.y += a2.x; d.z += a2.y; d.w += a2.z;

    d = f4add(d, ld4(bias, lane * 4));
    st4(out, idx, d);
}

extern "C" void kernel_launch(void* const* d_in, const int* in_sizes, int n_in,
                              void* d_out, int out_size) {
    const float* x   = (const float*)d_in[0];   // (8, 2048, 128)
    const float* lam = (const float*)d_in[1];   // (1, 1)
    const float* b   = (const float*)d_in[2];   // (1, 1, 128)
    float* out = (float*)d_out;

    const int vblocks = (NN / 4 + NTHREADS - 1) / NTHREADS;   // 2048
    const int fblocks = TT / TTILE;                           // 1024

    k_first<<<vblocks, NTHREADS>>>(x, lam);

    for (int it = 0; it < NFUSED; ++it) {
        if ((it & 1) == 0)
            k_fused<true><<<fblocks, NTHREADS>>>(lam);   // A -> B
        else
            k_fused<false><<<fblocks, NTHREADS>>>(lam);  // B -> A
    }

    k_final<<<vblocks, NTHREADS>>>(x, b, out);
}